// round 6
// baseline (speedup 1.0000x reference)
#include <cuda_runtime.h>
#include <cuda_bf16.h>
#include <cstdint>

#define C 128
#define LDW 132            // u32 row stride of data regions
#define THREADS 512
#define EPSF 1e-8f

__device__ float g_Mm[C * C];
__device__ float g_Md[C * C];
// B fragments, nt-contiguous: [k2*128 + c32*32 + g*4 + nt] = pack{W[2k2][n], W[2k2+1][n]},
// n = c32*32 + nt*8 + g
__device__ __align__(16) uint32_t g_BH[6][64 * C];
__device__ __align__(16) uint32_t g_BL[6][64 * C];

__device__ __forceinline__ void split_pack(float x0, float x1, uint32_t& h, uint32_t& l) {
    uint32_t u0 = __float_as_uint(x0), u1 = __float_as_uint(x1);
    h = __byte_perm(u0, u1, 0x7632);  // {top16(x0), top16(x1)}
    float l0 = x0 - __uint_as_float(u0 & 0xFFFF0000u);
    float l1 = x1 - __uint_as_float(u1 & 0xFFFF0000u);
    __nv_bfloat162 t = __floats2bfloat162_rn(l0, l1);
    l = *(uint32_t*)&t;
}
__device__ __forceinline__ uint2 pack2(float x, float y) {
    uint2 r;
    split_pack(x, y, r.x, r.y);
    return r;
}
__device__ __forceinline__ float2 unpack2(uint2 p) {
    float2 a = __bfloat1622float2(*(__nv_bfloat162*)&p.x);
    float2 b = __bfloat1622float2(*(__nv_bfloat162*)&p.y);
    return make_float2(a.x + b.x, a.y + b.y);
}

__global__ void precompute_M_kernel(const float* __restrict__ Wq_m, const float* __restrict__ Wk_m,
                                    const float* __restrict__ Wq_d, const float* __restrict__ Wk_d) {
    const float* Wq = blockIdx.y ? Wq_d : Wq_m;
    const float* Wk = blockIdx.y ? Wk_d : Wk_m;
    float* M = blockIdx.y ? g_Md : g_Mm;
    int i = blockIdx.x, t = threadIdx.x;
    __shared__ float qrow[C];
    qrow[t] = Wq[i * C + t];
    __syncthreads();
    const float* wkr = Wk + t * C;
    float acc = 0.f;
#pragma unroll 8
    for (int j = 0; j < C; j++) acc += qrow[j] * wkr[j];
    M[i * C + t] = acc * 0.08838834764831845f;
}

__global__ void bake_kernel(const float* __restrict__ Wg, const float* __restrict__ Wvm,
                            const float* __restrict__ Wvd, const float* __restrict__ W1) {
    int w = blockIdx.y;
    const float* src = (w == 0) ? Wg : (w == 1) ? g_Mm : (w == 2) ? Wvm
                      : (w == 3) ? g_Md : (w == 4) ? Wvd : W1;
    int idx = blockIdx.x * blockDim.x + threadIdx.x;  // 0..8191
    int nt = idx & 3, g = (idx >> 2) & 7, c32 = (idx >> 5) & 3, k2 = idx >> 7;
    int n = c32 * 32 + nt * 8 + g;
    uint32_t h, l;
    split_pack(src[(2 * k2) * C + n], src[(2 * k2 + 1) * C + n], h, l);
    g_BH[w][idx] = h;
    g_BL[w][idx] = l;
}

__device__ __forceinline__ void mma16816(float* d, const uint32_t* a, uint32_t b0, uint32_t b1) {
    asm volatile(
        "mma.sync.aligned.m16n8k16.row.col.f32.bf16.bf16.f32 "
        "{%0,%1,%2,%3}, {%4,%5,%6,%7}, {%8,%9}, {%0,%1,%2,%3};"
        : "+f"(d[0]), "+f"(d[1]), "+f"(d[2]), "+f"(d[3])
        : "r"(a[0]), "r"(a[1]), "r"(a[2]), "r"(a[3]), "r"(b0), "r"(b1));
}

#define MMA3(accn, bh0, bh1, bl0, bl1)     \
    do {                                   \
        mma16816(accn, ah, bh0, bh1);      \
        mma16816(accn, al, bh0, bh1);      \
        mma16816(accn, ah, bl0, bl1);      \
    } while (0)

// D[64,128] = (Ah+Al) @ W ; A packed interleaved {h,l} u32 pairs, row stride LDW.
// 16 warps: rows ((w&3)*16), cols (w>>2)*32. D may alias A or B region (stores post-sync).
__device__ void wgemm(const uint32_t* P, const uint32_t* BH, const uint32_t* BL, float* D,
                      int tid) {
    const int lane = tid & 31;
    const int rb = ((tid >> 5) & 3) * 16, c32 = tid >> 7;
    const int g = lane >> 2, t = lane & 3;
    float acc[4][4] = {};
    const uint32_t* pa = P + (rb + g) * LDW + 2 * t;
    const uint32_t* pb = BH + t * C + c32 * 32 + g * 4;
    const uint32_t* pc = BL + t * C + c32 * 32 + g * 4;
#pragma unroll 2
    for (int k0 = 0; k0 < 8; k0++) {
        uint2 a0 = *(const uint2*)(pa);
        uint2 a1 = *(const uint2*)(pa + 8 * LDW);
        uint2 a2 = *(const uint2*)(pa + 8);
        uint2 a3 = *(const uint2*)(pa + 8 * LDW + 8);
        uint4 bh0 = *(const uint4*)(pb);
        uint4 bh1 = *(const uint4*)(pb + 512);
        uint4 bl0 = *(const uint4*)(pc);
        uint4 bl1 = *(const uint4*)(pc + 512);
        uint32_t ah[4] = {a0.x, a1.x, a2.x, a3.x};
        uint32_t al[4] = {a0.y, a1.y, a2.y, a3.y};
        MMA3(acc[0], bh0.x, bh1.x, bl0.x, bl1.x);
        MMA3(acc[1], bh0.y, bh1.y, bl0.y, bl1.y);
        MMA3(acc[2], bh0.z, bh1.z, bl0.z, bl1.z);
        MMA3(acc[3], bh0.w, bh1.w, bl0.w, bl1.w);
        pa += 16;
        pb += 1024;
        pc += 1024;
    }
    __syncthreads();
    float* Dp = D + (rb + g) * LDW + c32 * 32 + 2 * t;
#pragma unroll
    for (int nt = 0; nt < 4; nt++) {
        *(float2*)(Dp + nt * 8) = make_float2(acc[nt][0], acc[nt][1]);
        *(float2*)(Dp + nt * 8 + 8 * LDW) = make_float2(acc[nt][2], acc[nt][3]);
    }
    __syncthreads();
}

// two GEMMs sharing one B pass (GCN): D0 = A0@W, D1 = A1@W
__device__ void wgemm2(const uint32_t* P0, const uint32_t* P1, const uint32_t* BH,
                       const uint32_t* BL, float* D0, float* D1, int tid) {
    const int lane = tid & 31;
    const int rb = ((tid >> 5) & 3) * 16, c32 = tid >> 7;
    const int g = lane >> 2, t = lane & 3;
    float acc0[4][4] = {}, acc1[4][4] = {};
    const uint32_t* pa = P0 + (rb + g) * LDW + 2 * t;
    const uint32_t* pq = P1 + (rb + g) * LDW + 2 * t;
    const uint32_t* pb = BH + t * C + c32 * 32 + g * 4;
    const uint32_t* pc = BL + t * C + c32 * 32 + g * 4;
#pragma unroll 1
    for (int k0 = 0; k0 < 8; k0++) {
        uint4 bh0 = *(const uint4*)(pb);
        uint4 bh1 = *(const uint4*)(pb + 512);
        uint4 bl0 = *(const uint4*)(pc);
        uint4 bl1 = *(const uint4*)(pc + 512);
        {
            uint2 a0 = *(const uint2*)(pa);
            uint2 a1 = *(const uint2*)(pa + 8 * LDW);
            uint2 a2 = *(const uint2*)(pa + 8);
            uint2 a3 = *(const uint2*)(pa + 8 * LDW + 8);
            uint32_t ah[4] = {a0.x, a1.x, a2.x, a3.x};
            uint32_t al[4] = {a0.y, a1.y, a2.y, a3.y};
            MMA3(acc0[0], bh0.x, bh1.x, bl0.x, bl1.x);
            MMA3(acc0[1], bh0.y, bh1.y, bl0.y, bl1.y);
            MMA3(acc0[2], bh0.z, bh1.z, bl0.z, bl1.z);
            MMA3(acc0[3], bh0.w, bh1.w, bl0.w, bl1.w);
        }
        {
            uint2 a0 = *(const uint2*)(pq);
            uint2 a1 = *(const uint2*)(pq + 8 * LDW);
            uint2 a2 = *(const uint2*)(pq + 8);
            uint2 a3 = *(const uint2*)(pq + 8 * LDW + 8);
            uint32_t ah[4] = {a0.x, a1.x, a2.x, a3.x};
            uint32_t al[4] = {a0.y, a1.y, a2.y, a3.y};
            MMA3(acc1[0], bh0.x, bh1.x, bl0.x, bl1.x);
            MMA3(acc1[1], bh0.y, bh1.y, bl0.y, bl1.y);
            MMA3(acc1[2], bh0.z, bh1.z, bl0.z, bl1.z);
            MMA3(acc1[3], bh0.w, bh1.w, bl0.w, bl1.w);
        }
        pa += 16;
        pq += 16;
        pb += 1024;
        pc += 1024;
    }
    __syncthreads();
    float* Dp = D0 + (rb + g) * LDW + c32 * 32 + 2 * t;
    float* Dq = D1 + (rb + g) * LDW + c32 * 32 + 2 * t;
#pragma unroll
    for (int nt = 0; nt < 4; nt++) {
        *(float2*)(Dp + nt * 8) = make_float2(acc0[nt][0], acc0[nt][1]);
        *(float2*)(Dp + nt * 8 + 8 * LDW) = make_float2(acc0[nt][2], acc0[nt][3]);
        *(float2*)(Dq + nt * 8) = make_float2(acc1[nt][0], acc1[nt][1]);
        *(float2*)(Dq + nt * 8 + 8 * LDW) = make_float2(acc1[nt][2], acc1[nt][3]);
    }
    __syncthreads();
}

__global__ void __launch_bounds__(THREADS, 1)
fused_kernel(const float* __restrict__ em, const float* __restrict__ ed,
             const float* __restrict__ W2, float* __restrict__ out) {
    extern __shared__ uint32_t sm[];
    uint32_t* R0 = sm;                  // em fp32 -> mLA fp32
    uint32_t* R1 = R0 + 64 * LDW;       // ed fp32 -> dLA fp32
    uint32_t* R2 = R1 + 64 * LDW;       // em_p -> g0 -> x0_p -> u_m_p -> ne_p
    uint32_t* R3 = R2 + 64 * LDW;       // ed_p -> g1 -> x1_p -> u_d_p
    uint32_t* WB = R3 + 64 * LDW;       // 16384: weight hi|lo planes; alias T/H fp32
    float* sW2 = (float*)(WB + 16384);
    float* F0 = (float*)R0;
    float* F1 = (float*)R1;
    float* sT = (float*)WB;

    const int tid = threadIdx.x;
    const int lane = tid & 31;
    const int row0 = (tid >> 5) * 4;    // 16 warps x 4 rows
    const long base = (long)blockIdx.x * 64;

    {   // load em/ed tiles
        const float4* ge = (const float4*)(em + base * C);
        const float4* gd = (const float4*)(ed + base * C);
        for (int i = tid; i < 64 * 32; i += THREADS) {
            int r = i >> 5, c4 = i & 31;
            ((float4*)(F0 + r * LDW))[c4] = ge[i];
            ((float4*)(F1 + r * LDW))[c4] = gd[i];
        }
        if (tid < C) sW2[tid] = W2[tid];
    }
    __syncthreads();

    // adjacency scalars + pack em/ed into R2/R3
    float aS[4], bS[4];
#pragma unroll
    for (int rr = 0; rr < 4; rr++) {
        int r = row0 + rr;
        const float* pe = F0 + r * LDW;
        const float* pd = F1 + r * LDW;
        float2 e0 = *(const float2*)(pe + 2 * lane), e1 = *(const float2*)(pe + 2 * lane + 64);
        float2 d0 = *(const float2*)(pd + 2 * lane), d1 = *(const float2*)(pd + 2 * lane + 64);
        float sa = fabsf(e0.x - d0.x) + fabsf(e0.y - d0.y) + fabsf(e1.x - d1.x) + fabsf(e1.y - d1.y);
        float q0 = e0.x * e0.x + e0.y * e0.y + e1.x * e1.x + e1.y * e1.y;
        float q1 = d0.x * d0.x + d0.y * d0.y + d1.x * d1.x + d1.y * d1.y;
        float dp = e0.x * d0.x + e0.y * d0.y + e1.x * d1.x + e1.y * d1.y;
#pragma unroll
        for (int o = 16; o; o >>= 1) {
            sa += __shfl_xor_sync(~0u, sa, o);
            q0 += __shfl_xor_sync(~0u, q0, o);
            q1 += __shfl_xor_sync(~0u, q1, o);
            dp += __shfl_xor_sync(~0u, dp, o);
        }
        float m = sa;
        float cosv = dp / (sqrtf(q0 + EPSF) * sqrtf(q1 + EPSF));
        float cp = cosv > 0.f ? cosv : 0.01f * cosv;
        aS[rr] = fminf(1.f / (1.f + cp), 1.f / (1.f + m));
        bS[rr] = fminf(cp / (1.f + cp), m / (1.f + m));
        *(uint2*)(R2 + r * LDW + 2 * lane) = pack2(e0.x, e0.y);
        *(uint2*)(R2 + r * LDW + 2 * lane + 64) = pack2(e1.x, e1.y);
        *(uint2*)(R3 + r * LDW + 2 * lane) = pack2(d0.x, d0.y);
        *(uint2*)(R3 + r * LDW + 2 * lane + 64) = pack2(d1.x, d1.y);
    }

    auto load_w = [&](int w) {
        __syncthreads();
        const uint4* gh = (const uint4*)g_BH[w];
        const uint4* gl = (const uint4*)g_BL[w];
        uint4* dh = (uint4*)WB;
        uint4* dl = (uint4*)(WB + 8192);
        for (int i = tid; i < 2048; i += THREADS) {
            dh[i] = gh[i];
            dl[i] = gl[i];
        }
        __syncthreads();
    };

    // ---- GCN: g0,g1 in one shared-B pass; D aliases own A (safe) ----
    load_w(0);
    wgemm2(R2, R3, WB, WB + 8192, (float*)R2, (float*)R3, tid);
#pragma unroll
    for (int rr = 0; rr < 4; rr++) {  // epilogue: x0,x1 packed in-place over g0,g1
        int r = row0 + rr;
        float a = aS[rr], b = bS[rr];
        const float* pg = (const float*)R2 + r * LDW;
        const float* ph = (const float*)R3 + r * LDW;
        const float* pe = F0 + r * LDW;
        const float* pd = F1 + r * LDW;
        float2 g0a = *(const float2*)(pg + 2 * lane), g0b = *(const float2*)(pg + 2 * lane + 64);
        float2 g1a = *(const float2*)(ph + 2 * lane), g1b = *(const float2*)(ph + 2 * lane + 64);
        float2 e0 = *(const float2*)(pe + 2 * lane), e1 = *(const float2*)(pe + 2 * lane + 64);
        float2 d0 = *(const float2*)(pd + 2 * lane), d1 = *(const float2*)(pd + 2 * lane + 64);
        *(uint2*)(R2 + r * LDW + 2 * lane) =
            pack2(fmaxf(a * g0a.x + b * g1a.x, 0.f) + e0.x, fmaxf(a * g0a.y + b * g1a.y, 0.f) + e0.y);
        *(uint2*)(R2 + r * LDW + 2 * lane + 64) =
            pack2(fmaxf(a * g0b.x + b * g1b.x, 0.f) + e1.x, fmaxf(a * g0b.y + b * g1b.y, 0.f) + e1.y);
        *(uint2*)(R3 + r * LDW + 2 * lane) =
            pack2(fmaxf(b * g0a.x + a * g1a.x, 0.f) + d0.x, fmaxf(b * g0a.y + a * g1a.y, 0.f) + d0.y);
        *(uint2*)(R3 + r * LDW + 2 * lane + 64) =
            pack2(fmaxf(b * g0b.x + a * g1b.x, 0.f) + d1.x, fmaxf(b * g0b.y + a * g1b.y, 0.f) + d1.y);
    }

    // attention epilogue: scores from T (W-alias) + F + packed x; u packed in-place over x
    auto attn_epi = [&](const float* F, uint32_t* X) {
#pragma unroll
        for (int rr = 0; rr < 4; rr++) {
            int r = row0 + rr;
            float2 t0 = *(const float2*)(sT + r * LDW + 2 * lane);
            float2 t1 = *(const float2*)(sT + r * LDW + 2 * lane + 64);
            float2 f0 = *(const float2*)(F + r * LDW + 2 * lane);
            float2 f1 = *(const float2*)(F + r * LDW + 2 * lane + 64);
            float2 x0 = unpack2(*(const uint2*)(X + r * LDW + 2 * lane));
            float2 x1 = unpack2(*(const uint2*)(X + r * LDW + 2 * lane + 64));
            float s0 = t0.x * f0.x + t0.y * f0.y + t1.x * f1.x + t1.y * f1.y;
            float s1 = t0.x * x0.x + t0.y * x0.y + t1.x * x1.x + t1.y * x1.y;
#pragma unroll
            for (int o = 16; o; o >>= 1) {
                s0 += __shfl_xor_sync(~0u, s0, o);
                s1 += __shfl_xor_sync(~0u, s1, o);
            }
            float mx = fmaxf(s0, s1);
            float e0 = expf(s0 - mx), e1 = expf(s1 - mx);
            float inv = 1.f / (e0 + e1);
            float w0 = e0 * inv, w1 = e1 * inv;
            *(uint2*)(X + r * LDW + 2 * lane) = pack2(w0 * f0.x + w1 * x0.x, w0 * f0.y + w1 * x0.y);
            *(uint2*)(X + r * LDW + 2 * lane + 64) =
                pack2(w0 * f1.x + w1 * x1.x, w0 * f1.y + w1 * x1.y);
        }
    };

    // ---- m branch ----
    load_w(1);
    wgemm(R2, WB, WB + 8192, sT, tid);      // T_m -> W-alias
    attn_epi(F0, R2);                        // u_m packed -> R2
    load_w(2);
    wgemm(R2, WB, WB + 8192, F0, tid);      // mLA -> R0

    // ---- d branch ----
    load_w(3);
    wgemm(R3, WB, WB + 8192, sT, tid);
    attn_epi(F1, R3);
    load_w(4);
    wgemm(R3, WB, WB + 8192, F1, tid);      // dLA -> R1

    // ---- head ----
    __syncthreads();
#pragma unroll
    for (int rr = 0; rr < 4; rr++) {
        int r = row0 + rr;
        float2 m0 = *(const float2*)(F0 + r * LDW + 2 * lane);
        float2 m1 = *(const float2*)(F0 + r * LDW + 2 * lane + 64);
        float2 d0 = *(const float2*)(F1 + r * LDW + 2 * lane);
        float2 d1 = *(const float2*)(F1 + r * LDW + 2 * lane + 64);
        *(uint2*)(R2 + r * LDW + 2 * lane) = pack2(m0.x * d0.x, m0.y * d0.y);
        *(uint2*)(R2 + r * LDW + 2 * lane + 64) = pack2(m1.x * d1.x, m1.y * d1.y);
    }
    load_w(5);
    wgemm(R2, WB, WB + 8192, sT, tid);      // H -> W-alias
#pragma unroll
    for (int rr = 0; rr < 4; rr++) {
        int r = row0 + rr;
        float2 h0 = *(const float2*)(sT + r * LDW + 2 * lane);
        float2 h1 = *(const float2*)(sT + r * LDW + 2 * lane + 64);
        float2 wa = *(const float2*)(sW2 + 2 * lane);
        float2 wb = *(const float2*)(sW2 + 2 * lane + 64);
        float p = fmaxf(h0.x, 0.f) * wa.x + fmaxf(h0.y, 0.f) * wa.y +
                  fmaxf(h1.x, 0.f) * wb.x + fmaxf(h1.y, 0.f) * wb.y;
#pragma unroll
        for (int o = 16; o; o >>= 1) p += __shfl_xor_sync(~0u, p, o);
        if (lane == 0) out[base + r] = 1.f / (1.f + expf(-p));
    }
}

extern "C" void kernel_launch(void* const* d_in, const int* in_sizes, int n_in,
                              void* d_out, int out_size) {
    const float* em    = (const float*)d_in[0];
    const float* ed    = (const float*)d_in[1];
    const float* W_gcn = (const float*)d_in[2];
    const float* Wq_m  = (const float*)d_in[3];
    const float* Wk_m  = (const float*)d_in[4];
    const float* Wv_m  = (const float*)d_in[5];
    const float* Wq_d  = (const float*)d_in[6];
    const float* Wk_d  = (const float*)d_in[7];
    const float* Wv_d  = (const float*)d_in[8];
    const float* W1    = (const float*)d_in[9];
    const float* W2    = (const float*)d_in[10];
    float* out = (float*)d_out;

    const int B = in_sizes[0] / C;
    const int smem_bytes = (4 * 64 * LDW + 16384 + 128) * 4;  // 201216 B

    precompute_M_kernel<<<dim3(C, 2), C>>>(Wq_m, Wk_m, Wq_d, Wk_d);
    bake_kernel<<<dim3(8192 / 256, 6), 256>>>(W_gcn, Wv_m, Wv_d, W1);

    cudaFuncSetAttribute(fused_kernel,
                         cudaFuncAttributeMaxDynamicSharedMemorySize, smem_bytes);
    fused_kernel<<<B / 64, THREADS, smem_bytes>>>(em, ed, W2, out);
}

// round 7
// speedup vs baseline: 1.4884x; 1.4884x over previous
#include <cuda_runtime.h>
#include <cuda_bf16.h>
#include <cstdint>

#define C 128
#define LDW 132            // u32 row stride of data regions
#define WSTR 136           // u32 k2-row stride of smem weight planes (conflict-free uint4)
#define WPL (64 * WSTR)    // words per weight plane (8704)
#define THREADS 512
#define EPSF 1e-8f

__device__ float g_Mm[C * C];
__device__ float g_Md[C * C];
// B fragments, nt-contiguous: [k2*128 + c32*32 + g*4 + nt] = pack{W[2k2][n], W[2k2+1][n]},
// n = c32*32 + nt*8 + g
__device__ __align__(16) uint32_t g_BH[6][64 * C];
__device__ __align__(16) uint32_t g_BL[6][64 * C];

__device__ __forceinline__ void split_pack(float x0, float x1, uint32_t& h, uint32_t& l) {
    uint32_t u0 = __float_as_uint(x0), u1 = __float_as_uint(x1);
    h = __byte_perm(u0, u1, 0x7632);  // {top16(x0), top16(x1)}
    float l0 = x0 - __uint_as_float(u0 & 0xFFFF0000u);
    float l1 = x1 - __uint_as_float(u1 & 0xFFFF0000u);
    __nv_bfloat162 t = __floats2bfloat162_rn(l0, l1);
    l = *(uint32_t*)&t;
}
__device__ __forceinline__ uint2 pack2(float x, float y) {
    uint2 r;
    split_pack(x, y, r.x, r.y);
    return r;
}
__device__ __forceinline__ float2 unpack2(uint2 p) {
    float2 a = __bfloat1622float2(*(__nv_bfloat162*)&p.x);
    float2 b = __bfloat1622float2(*(__nv_bfloat162*)&p.y);
    return make_float2(a.x + b.x, a.y + b.y);
}

__global__ void precompute_M_kernel(const float* __restrict__ Wq_m, const float* __restrict__ Wk_m,
                                    const float* __restrict__ Wq_d, const float* __restrict__ Wk_d) {
    const float* Wq = blockIdx.y ? Wq_d : Wq_m;
    const float* Wk = blockIdx.y ? Wk_d : Wk_m;
    float* M = blockIdx.y ? g_Md : g_Mm;
    int i = blockIdx.x, t = threadIdx.x;
    __shared__ float qrow[C];
    qrow[t] = Wq[i * C + t];
    __syncthreads();
    const float* wkr = Wk + t * C;
    float acc = 0.f;
#pragma unroll 8
    for (int j = 0; j < C; j++) acc += qrow[j] * wkr[j];
    M[i * C + t] = acc * 0.08838834764831845f;
}

__global__ void bake_kernel(const float* __restrict__ Wg, const float* __restrict__ Wvm,
                            const float* __restrict__ Wvd, const float* __restrict__ W1) {
    int w = blockIdx.y;
    const float* src = (w == 0) ? Wg : (w == 1) ? g_Mm : (w == 2) ? Wvm
                      : (w == 3) ? g_Md : (w == 4) ? Wvd : W1;
    int idx = blockIdx.x * blockDim.x + threadIdx.x;  // 0..8191
    int nt = idx & 3, g = (idx >> 2) & 7, c32 = (idx >> 5) & 3, k2 = idx >> 7;
    int n = c32 * 32 + nt * 8 + g;
    uint32_t h, l;
    split_pack(src[(2 * k2) * C + n], src[(2 * k2 + 1) * C + n], h, l);
    g_BH[w][idx] = h;
    g_BL[w][idx] = l;
}

__device__ __forceinline__ void mma16816(float* d, const uint32_t* a, uint32_t b0, uint32_t b1) {
    asm volatile(
        "mma.sync.aligned.m16n8k16.row.col.f32.bf16.bf16.f32 "
        "{%0,%1,%2,%3}, {%4,%5,%6,%7}, {%8,%9}, {%0,%1,%2,%3};"
        : "+f"(d[0]), "+f"(d[1]), "+f"(d[2]), "+f"(d[3])
        : "r"(a[0]), "r"(a[1]), "r"(a[2]), "r"(a[3]), "r"(b0), "r"(b1));
}

#define MMA3(accn, bh0, bh1, bl0, bl1) \
    do {                               \
        mma16816(accn, ah, bh0, bh1);  \
        mma16816(accn, al, bh0, bh1);  \
        mma16816(accn, ah, bl0, bl1);  \
    } while (0)

// D[64,128] = (Ah+Al) @ W ; A packed interleaved {h,l} u32 pairs, row stride LDW.
// 16 warps: rows ((w&3)*16), cols (w>>2)*32. D may alias A or B region (stores post-sync).
__device__ void wgemm(const uint32_t* P, const uint32_t* BH, const uint32_t* BL, float* D,
                      int tid) {
    const int lane = tid & 31;
    const int rb = ((tid >> 5) & 3) * 16, c32 = tid >> 7;
    const int g = lane >> 2, t = lane & 3;
    float acc[4][4] = {};
    const uint32_t* pa = P + (rb + g) * LDW + 2 * t;
    const uint32_t* pb = BH + t * WSTR + c32 * 32 + g * 4;
    const uint32_t* pc = BL + t * WSTR + c32 * 32 + g * 4;
#pragma unroll 2
    for (int k0 = 0; k0 < 8; k0++) {
        uint2 a0 = *(const uint2*)(pa);
        uint2 a1 = *(const uint2*)(pa + 8 * LDW);
        uint2 a2 = *(const uint2*)(pa + 8);
        uint2 a3 = *(const uint2*)(pa + 8 * LDW + 8);
        uint4 bh0 = *(const uint4*)(pb);
        uint4 bh1 = *(const uint4*)(pb + 4 * WSTR);
        uint4 bl0 = *(const uint4*)(pc);
        uint4 bl1 = *(const uint4*)(pc + 4 * WSTR);
        uint32_t ah[4] = {a0.x, a1.x, a2.x, a3.x};
        uint32_t al[4] = {a0.y, a1.y, a2.y, a3.y};
        MMA3(acc[0], bh0.x, bh1.x, bl0.x, bl1.x);
        MMA3(acc[1], bh0.y, bh1.y, bl0.y, bl1.y);
        MMA3(acc[2], bh0.z, bh1.z, bl0.z, bl1.z);
        MMA3(acc[3], bh0.w, bh1.w, bl0.w, bl1.w);
        pa += 16;
        pb += 8 * WSTR;
        pc += 8 * WSTR;
    }
    __syncthreads();
    float* Dp = D + (rb + g) * LDW + c32 * 32 + 2 * t;
#pragma unroll
    for (int nt = 0; nt < 4; nt++) {
        *(float2*)(Dp + nt * 8) = make_float2(acc[nt][0], acc[nt][1]);
        *(float2*)(Dp + nt * 8 + 8 * LDW) = make_float2(acc[nt][2], acc[nt][3]);
    }
    __syncthreads();
}

// two GEMMs sharing one B pass (GCN): D0 = A0@W, D1 = A1@W
__device__ void wgemm2(const uint32_t* P0, const uint32_t* P1, const uint32_t* BH,
                       const uint32_t* BL, float* D0, float* D1, int tid) {
    const int lane = tid & 31;
    const int rb = ((tid >> 5) & 3) * 16, c32 = tid >> 7;
    const int g = lane >> 2, t = lane & 3;
    float acc0[4][4] = {}, acc1[4][4] = {};
    const uint32_t* pa = P0 + (rb + g) * LDW + 2 * t;
    const uint32_t* pq = P1 + (rb + g) * LDW + 2 * t;
    const uint32_t* pb = BH + t * WSTR + c32 * 32 + g * 4;
    const uint32_t* pc = BL + t * WSTR + c32 * 32 + g * 4;
#pragma unroll 1
    for (int k0 = 0; k0 < 8; k0++) {
        uint4 bh0 = *(const uint4*)(pb);
        uint4 bh1 = *(const uint4*)(pb + 4 * WSTR);
        uint4 bl0 = *(const uint4*)(pc);
        uint4 bl1 = *(const uint4*)(pc + 4 * WSTR);
        {
            uint2 a0 = *(const uint2*)(pa);
            uint2 a1 = *(const uint2*)(pa + 8 * LDW);
            uint2 a2 = *(const uint2*)(pa + 8);
            uint2 a3 = *(const uint2*)(pa + 8 * LDW + 8);
            uint32_t ah[4] = {a0.x, a1.x, a2.x, a3.x};
            uint32_t al[4] = {a0.y, a1.y, a2.y, a3.y};
            MMA3(acc0[0], bh0.x, bh1.x, bl0.x, bl1.x);
            MMA3(acc0[1], bh0.y, bh1.y, bl0.y, bl1.y);
            MMA3(acc0[2], bh0.z, bh1.z, bl0.z, bl1.z);
            MMA3(acc0[3], bh0.w, bh1.w, bl0.w, bl1.w);
        }
        {
            uint2 a0 = *(const uint2*)(pq);
            uint2 a1 = *(const uint2*)(pq + 8 * LDW);
            uint2 a2 = *(const uint2*)(pq + 8);
            uint2 a3 = *(const uint2*)(pq + 8 * LDW + 8);
            uint32_t ah[4] = {a0.x, a1.x, a2.x, a3.x};
            uint32_t al[4] = {a0.y, a1.y, a2.y, a3.y};
            MMA3(acc1[0], bh0.x, bh1.x, bl0.x, bl1.x);
            MMA3(acc1[1], bh0.y, bh1.y, bl0.y, bl1.y);
            MMA3(acc1[2], bh0.z, bh1.z, bl0.z, bl1.z);
            MMA3(acc1[3], bh0.w, bh1.w, bl0.w, bl1.w);
        }
        pa += 16;
        pq += 16;
        pb += 8 * WSTR;
        pc += 8 * WSTR;
    }
    __syncthreads();
    float* Dp = D0 + (rb + g) * LDW + c32 * 32 + 2 * t;
    float* Dq = D1 + (rb + g) * LDW + c32 * 32 + 2 * t;
#pragma unroll
    for (int nt = 0; nt < 4; nt++) {
        *(float2*)(Dp + nt * 8) = make_float2(acc0[nt][0], acc0[nt][1]);
        *(float2*)(Dp + nt * 8 + 8 * LDW) = make_float2(acc0[nt][2], acc0[nt][3]);
        *(float2*)(Dq + nt * 8) = make_float2(acc1[nt][0], acc1[nt][1]);
        *(float2*)(Dq + nt * 8 + 8 * LDW) = make_float2(acc1[nt][2], acc1[nt][3]);
    }
    __syncthreads();
}

__global__ void __launch_bounds__(THREADS, 1)
fused_kernel(const float* __restrict__ em, const float* __restrict__ ed,
             const float* __restrict__ W2, float* __restrict__ out) {
    extern __shared__ uint32_t sm[];
    uint32_t* R0 = sm;                  // em fp32 -> mLA fp32
    uint32_t* R1 = R0 + 64 * LDW;       // ed fp32 -> dLA fp32
    uint32_t* R2 = R1 + 64 * LDW;       // em_p -> g0 -> x0_p -> u_m_p -> ne_p
    uint32_t* R3 = R2 + 64 * LDW;       // ed_p -> g1 -> x1_p -> u_d_p
    uint32_t* WB = R3 + 64 * LDW;       // 2*WPL: weight hi|lo planes; alias T/H fp32
    float* sW2 = (float*)(WB + 2 * WPL);
    float* F0 = (float*)R0;
    float* F1 = (float*)R1;
    float* sT = (float*)WB;

    const int tid = threadIdx.x;
    const int lane = tid & 31;
    const int row0 = (tid >> 5) * 4;    // 16 warps x 4 rows
    const long base = (long)blockIdx.x * 64;

    {   // load em/ed tiles
        const float4* ge = (const float4*)(em + base * C);
        const float4* gd = (const float4*)(ed + base * C);
        for (int i = tid; i < 64 * 32; i += THREADS) {
            int r = i >> 5, c4 = i & 31;
            ((float4*)(F0 + r * LDW))[c4] = ge[i];
            ((float4*)(F1 + r * LDW))[c4] = gd[i];
        }
        if (tid < C) sW2[tid] = W2[tid];
    }
    __syncthreads();

    // adjacency scalars + pack em/ed into R2/R3
    float aS[4], bS[4];
#pragma unroll
    for (int rr = 0; rr < 4; rr++) {
        int r = row0 + rr;
        const float* pe = F0 + r * LDW;
        const float* pd = F1 + r * LDW;
        float2 e0 = *(const float2*)(pe + 2 * lane), e1 = *(const float2*)(pe + 2 * lane + 64);
        float2 d0 = *(const float2*)(pd + 2 * lane), d1 = *(const float2*)(pd + 2 * lane + 64);
        float sa = fabsf(e0.x - d0.x) + fabsf(e0.y - d0.y) + fabsf(e1.x - d1.x) + fabsf(e1.y - d1.y);
        float q0 = e0.x * e0.x + e0.y * e0.y + e1.x * e1.x + e1.y * e1.y;
        float q1 = d0.x * d0.x + d0.y * d0.y + d1.x * d1.x + d1.y * d1.y;
        float dp = e0.x * d0.x + e0.y * d0.y + e1.x * d1.x + e1.y * d1.y;
#pragma unroll
        for (int o = 16; o; o >>= 1) {
            sa += __shfl_xor_sync(~0u, sa, o);
            q0 += __shfl_xor_sync(~0u, q0, o);
            q1 += __shfl_xor_sync(~0u, q1, o);
            dp += __shfl_xor_sync(~0u, dp, o);
        }
        float m = sa;
        float cosv = dp / (sqrtf(q0 + EPSF) * sqrtf(q1 + EPSF));
        float cp = cosv > 0.f ? cosv : 0.01f * cosv;
        aS[rr] = fminf(1.f / (1.f + cp), 1.f / (1.f + m));
        bS[rr] = fminf(cp / (1.f + cp), m / (1.f + m));
        *(uint2*)(R2 + r * LDW + 2 * lane) = pack2(e0.x, e0.y);
        *(uint2*)(R2 + r * LDW + 2 * lane + 64) = pack2(e1.x, e1.y);
        *(uint2*)(R3 + r * LDW + 2 * lane) = pack2(d0.x, d0.y);
        *(uint2*)(R3 + r * LDW + 2 * lane + 64) = pack2(d1.x, d1.y);
    }

    auto load_w = [&](int w) {
        __syncthreads();
        const uint4* gh = (const uint4*)g_BH[w];
        const uint4* gl = (const uint4*)g_BL[w];
        uint4* dh = (uint4*)WB;  // padded: k2-row = 34 uint4 (WSTR u32)
        uint4* dl = (uint4*)(WB + WPL);
        for (int i = tid; i < 2048; i += THREADS) {
            int k2 = i >> 5, c = i & 31;
            dh[k2 * (WSTR / 4) + c] = gh[i];
            dl[k2 * (WSTR / 4) + c] = gl[i];
        }
        __syncthreads();
    };

    // ---- GCN: g0,g1 in one shared-B pass; D aliases own A (safe) ----
    load_w(0);
    wgemm2(R2, R3, WB, WB + WPL, (float*)R2, (float*)R3, tid);
#pragma unroll
    for (int rr = 0; rr < 4; rr++) {  // epilogue: x0,x1 packed in-place over g0,g1
        int r = row0 + rr;
        float a = aS[rr], b = bS[rr];
        const float* pg = (const float*)R2 + r * LDW;
        const float* ph = (const float*)R3 + r * LDW;
        const float* pe = F0 + r * LDW;
        const float* pd = F1 + r * LDW;
        float2 g0a = *(const float2*)(pg + 2 * lane), g0b = *(const float2*)(pg + 2 * lane + 64);
        float2 g1a = *(const float2*)(ph + 2 * lane), g1b = *(const float2*)(ph + 2 * lane + 64);
        float2 e0 = *(const float2*)(pe + 2 * lane), e1 = *(const float2*)(pe + 2 * lane + 64);
        float2 d0 = *(const float2*)(pd + 2 * lane), d1 = *(const float2*)(pd + 2 * lane + 64);
        *(uint2*)(R2 + r * LDW + 2 * lane) =
            pack2(fmaxf(a * g0a.x + b * g1a.x, 0.f) + e0.x, fmaxf(a * g0a.y + b * g1a.y, 0.f) + e0.y);
        *(uint2*)(R2 + r * LDW + 2 * lane + 64) =
            pack2(fmaxf(a * g0b.x + b * g1b.x, 0.f) + e1.x, fmaxf(a * g0b.y + b * g1b.y, 0.f) + e1.y);
        *(uint2*)(R3 + r * LDW + 2 * lane) =
            pack2(fmaxf(b * g0a.x + a * g1a.x, 0.f) + d0.x, fmaxf(b * g0a.y + a * g1a.y, 0.f) + d0.y);
        *(uint2*)(R3 + r * LDW + 2 * lane + 64) =
            pack2(fmaxf(b * g0b.x + a * g1b.x, 0.f) + d1.x, fmaxf(b * g0b.y + a * g1b.y, 0.f) + d1.y);
    }

    // attention epilogue: scores from T (W-alias) + F + packed x; u packed in-place over x
    auto attn_epi = [&](const float* F, uint32_t* X) {
#pragma unroll
        for (int rr = 0; rr < 4; rr++) {
            int r = row0 + rr;
            float2 t0 = *(const float2*)(sT + r * LDW + 2 * lane);
            float2 t1 = *(const float2*)(sT + r * LDW + 2 * lane + 64);
            float2 f0 = *(const float2*)(F + r * LDW + 2 * lane);
            float2 f1 = *(const float2*)(F + r * LDW + 2 * lane + 64);
            float2 x0 = unpack2(*(const uint2*)(X + r * LDW + 2 * lane));
            float2 x1 = unpack2(*(const uint2*)(X + r * LDW + 2 * lane + 64));
            float s0 = t0.x * f0.x + t0.y * f0.y + t1.x * f1.x + t1.y * f1.y;
            float s1 = t0.x * x0.x + t0.y * x0.y + t1.x * x1.x + t1.y * x1.y;
#pragma unroll
            for (int o = 16; o; o >>= 1) {
                s0 += __shfl_xor_sync(~0u, s0, o);
                s1 += __shfl_xor_sync(~0u, s1, o);
            }
            float mx = fmaxf(s0, s1);
            float e0 = expf(s0 - mx), e1 = expf(s1 - mx);
            float inv = 1.f / (e0 + e1);
            float w0 = e0 * inv, w1 = e1 * inv;
            *(uint2*)(X + r * LDW + 2 * lane) = pack2(w0 * f0.x + w1 * x0.x, w0 * f0.y + w1 * x0.y);
            *(uint2*)(X + r * LDW + 2 * lane + 64) =
                pack2(w0 * f1.x + w1 * x1.x, w0 * f1.y + w1 * x1.y);
        }
    };

    // ---- m branch ----
    load_w(1);
    wgemm(R2, WB, WB + WPL, sT, tid);   // T_m -> W-alias
    attn_epi(F0, R2);                    // u_m packed -> R2
    load_w(2);
    wgemm(R2, WB, WB + WPL, F0, tid);   // mLA -> R0

    // ---- d branch ----
    load_w(3);
    wgemm(R3, WB, WB + WPL, sT, tid);
    attn_epi(F1, R3);
    load_w(4);
    wgemm(R3, WB, WB + WPL, F1, tid);   // dLA -> R1

    // ---- head ----
    __syncthreads();
#pragma unroll
    for (int rr = 0; rr < 4; rr++) {
        int r = row0 + rr;
        float2 m0 = *(const float2*)(F0 + r * LDW + 2 * lane);
        float2 m1 = *(const float2*)(F0 + r * LDW + 2 * lane + 64);
        float2 d0 = *(const float2*)(F1 + r * LDW + 2 * lane);
        float2 d1 = *(const float2*)(F1 + r * LDW + 2 * lane + 64);
        *(uint2*)(R2 + r * LDW + 2 * lane) = pack2(m0.x * d0.x, m0.y * d0.y);
        *(uint2*)(R2 + r * LDW + 2 * lane + 64) = pack2(m1.x * d1.x, m1.y * d1.y);
    }
    load_w(5);
    wgemm(R2, WB, WB + WPL, sT, tid);   // H -> W-alias
#pragma unroll
    for (int rr = 0; rr < 4; rr++) {
        int r = row0 + rr;
        float2 h0 = *(const float2*)(sT + r * LDW + 2 * lane);
        float2 h1 = *(const float2*)(sT + r * LDW + 2 * lane + 64);
        float2 wa = *(const float2*)(sW2 + 2 * lane);
        float2 wb = *(const float2*)(sW2 + 2 * lane + 64);
        float p = fmaxf(h0.x, 0.f) * wa.x + fmaxf(h0.y, 0.f) * wa.y +
                  fmaxf(h1.x, 0.f) * wb.x + fmaxf(h1.y, 0.f) * wb.y;
#pragma unroll
        for (int o = 16; o; o >>= 1) p += __shfl_xor_sync(~0u, p, o);
        if (lane == 0) out[base + r] = 1.f / (1.f + expf(-p));
    }
}

extern "C" void kernel_launch(void* const* d_in, const int* in_sizes, int n_in,
                              void* d_out, int out_size) {
    const float* em    = (const float*)d_in[0];
    const float* ed    = (const float*)d_in[1];
    const float* W_gcn = (const float*)d_in[2];
    const float* Wq_m  = (const float*)d_in[3];
    const float* Wk_m  = (const float*)d_in[4];
    const float* Wv_m  = (const float*)d_in[5];
    const float* Wq_d  = (const float*)d_in[6];
    const float* Wk_d  = (const float*)d_in[7];
    const float* Wv_d  = (const float*)d_in[8];
    const float* W1    = (const float*)d_in[9];
    const float* W2    = (const float*)d_in[10];
    float* out = (float*)d_out;

    const int B = in_sizes[0] / C;
    const int smem_bytes = (4 * 64 * LDW + 2 * WPL + 128) * 4;  // 205,312 B

    precompute_M_kernel<<<dim3(C, 2), C>>>(Wq_m, Wk_m, Wq_d, Wk_d);
    bake_kernel<<<dim3(8192 / 256, 6), 256>>>(W_gcn, Wv_m, Wv_d, W1);

    cudaFuncSetAttribute(fused_kernel,
                         cudaFuncAttributeMaxDynamicSharedMemorySize, smem_bytes);
    fused_kernel<<<B / 64, THREADS, smem_bytes>>>(em, ed, W2, out);
}

// round 9
// speedup vs baseline: 1.8522x; 1.2444x over previous
#include <cuda_runtime.h>
#include <cuda_bf16.h>
#include <cstdint>

#define C 128
#define LDW 132
#define WSTR 136
#define WPL (64 * WSTR)
#define THREADS 512
#define EPSF 1e-8f

__device__ float g_Mm[C * C];
__device__ float g_Md[C * C];
// padded (WSTR) fragment images, ready for linear bulk copy into smem
__device__ __align__(16) uint32_t g_BH[6][WPL];
__device__ __align__(16) uint32_t g_BL[6][WPL];

// ---- smem u32 layout ----
#define U_F0 16
#define U_F1 (U_F0 + 8448)
#define U_R2 (U_F1 + 8448)
#define U_R3 (U_R2 + 8448)
#define U_WH (U_R3 + 8448)
#define U_WL (U_WH + WPL)
#define U_RED (U_WL + WPL)   // red0[256], red1[256]
#define U_W0B (U_RED + 512)
#define U_W1B (U_W0B + 64)
#define U_AB (U_W1B + 64)
#define U_BB (U_AB + 64)
#define U_W2 (U_BB + 64)
#define U_TOT (U_W2 + 128)   // 52112 u32 = 208448 B

__device__ __forceinline__ uint32_t s2u(const void* p) {
    uint32_t a;
    asm("{ .reg .u64 t; cvta.to.shared.u64 t, %1; cvt.u32.u64 %0, t; }" : "=r"(a) : "l"(p));
    return a;
}
#define MBAR_INIT(a, c) asm volatile("mbarrier.init.shared.b64 [%0], %1;" ::"r"(a), "r"(c) : "memory")
#define MBAR_EXPECT(a, b) \
    asm volatile("mbarrier.arrive.expect_tx.shared.b64 _, [%0], %1;" ::"r"(a), "r"(b) : "memory")
__device__ __forceinline__ void mbar_wait(uint32_t a, uint32_t par) {
    asm volatile(
        "{\n\t.reg .pred P;\n\tWL_%=:\n\t"
        "mbarrier.try_wait.parity.acquire.cta.shared::cta.b64 P, [%0], %1, 0x989680;\n\t"
        "@P bra.uni WD_%=;\n\tbra.uni WL_%=;\n\tWD_%=:\n\t}" ::"r"(a), "r"(par) : "memory");
}
__device__ __forceinline__ void bulk_g2s(uint32_t dst, const void* gsrc, uint32_t bytes,
                                         uint32_t mbar) {
    asm volatile(
        "{ .reg .u64 g; cvta.to.global.u64 g, %1;\n\t"
        "cp.async.bulk.shared::cluster.global.mbarrier::complete_tx::bytes [%0], [g], %2, [%3]; }"
        ::"r"(dst), "l"(gsrc), "r"(bytes), "r"(mbar) : "memory");
}

__device__ __forceinline__ void split_pack(float x0, float x1, uint32_t& h, uint32_t& l) {
    uint32_t u0 = __float_as_uint(x0), u1 = __float_as_uint(x1);
    h = __byte_perm(u0, u1, 0x7632);
    float l0 = x0 - __uint_as_float(u0 & 0xFFFF0000u);
    float l1 = x1 - __uint_as_float(u1 & 0xFFFF0000u);
    __nv_bfloat162 t = __floats2bfloat162_rn(l0, l1);
    l = *(uint32_t*)&t;
}
__device__ __forceinline__ uint2 pack2(float x, float y) {
    uint2 r;
    split_pack(x, y, r.x, r.y);
    return r;
}
__device__ __forceinline__ float2 unpack2(uint2 p) {
    float2 a = __bfloat1622float2(*(__nv_bfloat162*)&p.x);
    float2 b = __bfloat1622float2(*(__nv_bfloat162*)&p.y);
    return make_float2(a.x + b.x, a.y + b.y);
}
__device__ __forceinline__ void mma16816(float* d, const uint32_t* a, uint32_t b0, uint32_t b1) {
    asm volatile(
        "mma.sync.aligned.m16n8k16.row.col.f32.bf16.bf16.f32 "
        "{%0,%1,%2,%3}, {%4,%5,%6,%7}, {%8,%9}, {%0,%1,%2,%3};"
        : "+f"(d[0]), "+f"(d[1]), "+f"(d[2]), "+f"(d[3])
        : "r"(a[0]), "r"(a[1]), "r"(a[2]), "r"(a[3]), "r"(b0), "r"(b1));
}
#define MMA3(accn, bh0, bh1, bl0, bl1) \
    do {                               \
        mma16816(accn, ah, bh0, bh1);  \
        mma16816(accn, al, bh0, bh1);  \
        mma16816(accn, ah, bl0, bl1);  \
    } while (0)

// acc[nt][0..3]: rows (rb+g, rb+g+8), cols c32*32+nt*8+2t (+1)
__device__ __forceinline__ void mma_block(const uint32_t* A, const uint32_t* WH,
                                          const uint32_t* WL, float acc[4][4], int rb, int c32,
                                          int g, int t) {
    const uint32_t* pa = A + (rb + g) * LDW + 2 * t;
    const uint32_t* pb = WH + t * WSTR + c32 * 32 + g * 4;
    const uint32_t* pc = WL + t * WSTR + c32 * 32 + g * 4;
#pragma unroll 2
    for (int k0 = 0; k0 < 8; k0++) {
        uint2 a0 = *(const uint2*)pa, a1 = *(const uint2*)(pa + 8 * LDW);
        uint2 a2 = *(const uint2*)(pa + 8), a3 = *(const uint2*)(pa + 8 * LDW + 8);
        uint4 bh0 = *(const uint4*)pb, bh1 = *(const uint4*)(pb + 4 * WSTR);
        uint4 bl0 = *(const uint4*)pc, bl1 = *(const uint4*)(pc + 4 * WSTR);
        uint32_t ah[4] = {a0.x, a1.x, a2.x, a3.x}, al[4] = {a0.y, a1.y, a2.y, a3.y};
        MMA3(acc[0], bh0.x, bh1.x, bl0.x, bl1.x);
        MMA3(acc[1], bh0.y, bh1.y, bl0.y, bl1.y);
        MMA3(acc[2], bh0.z, bh1.z, bl0.z, bl1.z);
        MMA3(acc[3], bh0.w, bh1.w, bl0.w, bl1.w);
        pa += 16;
        pb += 8 * WSTR;
        pc += 8 * WSTR;
    }
}
// dual-A version sharing one B pass (GCN)
__device__ __forceinline__ void mma_block2(const uint32_t* A0, const uint32_t* A1,
                                           const uint32_t* WH, const uint32_t* WL,
                                           float acc0[4][4], float acc1[4][4], int rb, int c32,
                                           int g, int t) {
    const uint32_t* pa = A0 + (rb + g) * LDW + 2 * t;
    const uint32_t* pq = A1 + (rb + g) * LDW + 2 * t;
    const uint32_t* pb = WH + t * WSTR + c32 * 32 + g * 4;
    const uint32_t* pc = WL + t * WSTR + c32 * 32 + g * 4;
#pragma unroll 1
    for (int k0 = 0; k0 < 8; k0++) {
        uint4 bh0 = *(const uint4*)pb, bh1 = *(const uint4*)(pb + 4 * WSTR);
        uint4 bl0 = *(const uint4*)pc, bl1 = *(const uint4*)(pc + 4 * WSTR);
        {
            uint2 a0 = *(const uint2*)pa, a1 = *(const uint2*)(pa + 8 * LDW);
            uint2 a2 = *(const uint2*)(pa + 8), a3 = *(const uint2*)(pa + 8 * LDW + 8);
            uint32_t ah[4] = {a0.x, a1.x, a2.x, a3.x}, al[4] = {a0.y, a1.y, a2.y, a3.y};
            MMA3(acc0[0], bh0.x, bh1.x, bl0.x, bl1.x);
            MMA3(acc0[1], bh0.y, bh1.y, bl0.y, bl1.y);
            MMA3(acc0[2], bh0.z, bh1.z, bl0.z, bl1.z);
            MMA3(acc0[3], bh0.w, bh1.w, bl0.w, bl1.w);
        }
        {
            uint2 a0 = *(const uint2*)pq, a1 = *(const uint2*)(pq + 8 * LDW);
            uint2 a2 = *(const uint2*)(pq + 8), a3 = *(const uint2*)(pq + 8 * LDW + 8);
            uint32_t ah[4] = {a0.x, a1.x, a2.x, a3.x}, al[4] = {a0.y, a1.y, a2.y, a3.y};
            MMA3(acc1[0], bh0.x, bh1.x, bl0.x, bl1.x);
            MMA3(acc1[1], bh0.y, bh1.y, bl0.y, bl1.y);
            MMA3(acc1[2], bh0.z, bh1.z, bl0.z, bl1.z);
            MMA3(acc1[3], bh0.w, bh1.w, bl0.w, bl1.w);
        }
        pa += 16;
        pq += 16;
        pb += 8 * WSTR;
        pc += 8 * WSTR;
    }
}

// ---------------- prep ----------------
__global__ void precompute_M_kernel(const float* __restrict__ Wq_m, const float* __restrict__ Wk_m,
                                    const float* __restrict__ Wq_d, const float* __restrict__ Wk_d) {
    const float* Wq = blockIdx.y ? Wq_d : Wq_m;
    const float* Wk = blockIdx.y ? Wk_d : Wk_m;
    float* M = blockIdx.y ? g_Md : g_Mm;
    int i = blockIdx.x, t = threadIdx.x;
    __shared__ float qrow[C];
    qrow[t] = Wq[i * C + t];
    __syncthreads();
    const float* wkr = Wk + t * C;
    float acc = 0.f;
#pragma unroll 8
    for (int j = 0; j < C; j++) acc += qrow[j] * wkr[j];
    M[i * C + t] = acc * 0.08838834764831845f;
}

__global__ void bake_kernel(const float* __restrict__ Wg, const float* __restrict__ Wvm,
                            const float* __restrict__ Wvd, const float* __restrict__ W1) {
    int w = blockIdx.y;
    const float* src = (w == 0) ? Wg : (w == 1) ? g_Mm : (w == 2) ? Wvm
                      : (w == 3) ? g_Md : (w == 4) ? Wvd : W1;
    int idx = blockIdx.x * blockDim.x + threadIdx.x;  // 0..8191
    int nt = idx & 3, g = (idx >> 2) & 7, c32 = (idx >> 5) & 3, k2 = idx >> 7;
    int n = c32 * 32 + nt * 8 + g;
    uint32_t h, l;
    split_pack(src[(2 * k2) * C + n], src[(2 * k2 + 1) * C + n], h, l);
    int dst = k2 * WSTR + (idx & 127);  // padded image
    g_BH[w][dst] = h;
    g_BL[w][dst] = l;
}

// ---------------- fused ----------------
__global__ void __launch_bounds__(THREADS, 1)
fused_kernel(const float* __restrict__ em, const float* __restrict__ ed,
             const float* __restrict__ W2, float* __restrict__ out) {
    extern __shared__ uint32_t sm[];
    const uint32_t sb = s2u(sm);
    const uint32_t mb = sb;  // mbarrier at word 0
    float* F0 = (float*)(sm + U_F0);
    float* F1 = (float*)(sm + U_F1);
    uint32_t* R2 = sm + U_R2;
    uint32_t* R3 = sm + U_R3;
    uint32_t* WH = sm + U_WH;
    uint32_t* WL = sm + U_WL;
    float* red0 = (float*)(sm + U_RED);
    float* red1 = red0 + 256;
    float* w0B = (float*)(sm + U_W0B);
    float* w1B = (float*)(sm + U_W1B);
    float* aB = (float*)(sm + U_AB);
    float* bB = (float*)(sm + U_BB);
    float* sW2 = (float*)(sm + U_W2);

    const int tid = threadIdx.x;
    const int w = tid >> 5, lane = tid & 31;
    const int g = lane >> 2, t = lane & 3;
    const int rb = (w & 3) * 16, c32 = w >> 2;
    const int r1 = rb + g, r2 = r1 + 8;
    const int cb = c32 * 32 + 2 * t;  // col base (nt adds *8)
    const int row4 = w * 4;           // per-row epilogue mapping
    const long base = (long)blockIdx.x * 64;

    if (tid == 0) {
        MBAR_INIT(mb, 1);
        MBAR_EXPECT(mb, 2 * WPL * 4);
        bulk_g2s(sb + U_WH * 4, &g_BH[0][0], WPL * 4, mb);
        bulk_g2s(sb + U_WL * 4, &g_BL[0][0], WPL * 4, mb);
    }
    {  // load em/ed tiles (fp32 padded)
        const float4* ge = (const float4*)(em + base * C);
        const float4* gd = (const float4*)(ed + base * C);
        for (int i = tid; i < 64 * 32; i += THREADS) {
            int r = i >> 5, c4 = i & 31;
            ((float4*)(F0 + r * LDW))[c4] = ge[i];
            ((float4*)(F1 + r * LDW))[c4] = gd[i];
        }
        if (tid < C) sW2[tid] = W2[tid];
    }
    __syncthreads();

    // adjacency scalars -> aB/bB, pack em/ed -> R2/R3 (warp owns 4 rows)
#pragma unroll
    for (int rr = 0; rr < 4; rr++) {
        int r = row4 + rr;
        const float* pe = F0 + r * LDW;
        const float* pd = F1 + r * LDW;
        float2 e0 = *(const float2*)(pe + 2 * lane), e1 = *(const float2*)(pe + 2 * lane + 64);
        float2 d0 = *(const float2*)(pd + 2 * lane), d1 = *(const float2*)(pd + 2 * lane + 64);
        float sa = fabsf(e0.x - d0.x) + fabsf(e0.y - d0.y) + fabsf(e1.x - d1.x) + fabsf(e1.y - d1.y);
        float q0 = e0.x * e0.x + e0.y * e0.y + e1.x * e1.x + e1.y * e1.y;
        float q1 = d0.x * d0.x + d0.y * d0.y + d1.x * d1.x + d1.y * d1.y;
        float dp = e0.x * d0.x + e0.y * d0.y + e1.x * d1.x + e1.y * d1.y;
#pragma unroll
        for (int o = 16; o; o >>= 1) {
            sa += __shfl_xor_sync(~0u, sa, o);
            q0 += __shfl_xor_sync(~0u, q0, o);
            q1 += __shfl_xor_sync(~0u, q1, o);
            dp += __shfl_xor_sync(~0u, dp, o);
        }
        if (lane == 0) {
            float m = sa;
            float cosv = dp / (sqrtf(q0 + EPSF) * sqrtf(q1 + EPSF));
            float cp = cosv > 0.f ? cosv : 0.01f * cosv;
            aB[r] = fminf(1.f / (1.f + cp), 1.f / (1.f + m));
            bB[r] = fminf(cp / (1.f + cp), m / (1.f + m));
        }
        *(uint2*)(R2 + r * LDW + 2 * lane) = pack2(e0.x, e0.y);
        *(uint2*)(R2 + r * LDW + 2 * lane + 64) = pack2(e1.x, e1.y);
        *(uint2*)(R3 + r * LDW + 2 * lane) = pack2(d0.x, d0.y);
        *(uint2*)(R3 + r * LDW + 2 * lane + 64) = pack2(d1.x, d1.y);
    }
    __syncthreads();

    auto prefetch = [&](int nw) {
        if (tid == 0) {
            MBAR_EXPECT(mb, 2 * WPL * 4);
            bulk_g2s(sb + U_WH * 4, &g_BH[nw][0], WPL * 4, mb);
            bulk_g2s(sb + U_WL * 4, &g_BL[nw][0], WPL * 4, mb);
        }
    };

    // ---------------- stage 0: GCN ----------------
    mbar_wait(mb, 0);
    {
        float a0[4][4] = {}, a1[4][4] = {};
        mma_block2(R2, R3, WH, WL, a0, a1, rb, c32, g, t);
        __syncthreads();
        prefetch(1);
        float aa1 = aB[r1], bb1 = bB[r1], aa2 = aB[r2], bb2 = bB[r2];
#pragma unroll
        for (int nt = 0; nt < 4; nt++) {
            int c = cb + nt * 8;
            float2 e1v = *(const float2*)(F0 + r1 * LDW + c);
            float2 e2v = *(const float2*)(F0 + r2 * LDW + c);
            float2 d1v = *(const float2*)(F1 + r1 * LDW + c);
            float2 d2v = *(const float2*)(F1 + r2 * LDW + c);
            *(uint2*)(R2 + r1 * LDW + c) = pack2(fmaxf(aa1 * a0[nt][0] + bb1 * a1[nt][0], 0.f) + e1v.x,
                                                 fmaxf(aa1 * a0[nt][1] + bb1 * a1[nt][1], 0.f) + e1v.y);
            *(uint2*)(R2 + r2 * LDW + c) = pack2(fmaxf(aa2 * a0[nt][2] + bb2 * a1[nt][2], 0.f) + e2v.x,
                                                 fmaxf(aa2 * a0[nt][3] + bb2 * a1[nt][3], 0.f) + e2v.y);
            *(uint2*)(R3 + r1 * LDW + c) = pack2(fmaxf(bb1 * a0[nt][0] + aa1 * a1[nt][0], 0.f) + d1v.x,
                                                 fmaxf(bb1 * a0[nt][1] + aa1 * a1[nt][1], 0.f) + d1v.y);
            *(uint2*)(R3 + r2 * LDW + c) = pack2(fmaxf(bb2 * a0[nt][2] + aa2 * a1[nt][2], 0.f) + d2v.x,
                                                 fmaxf(bb2 * a0[nt][3] + aa2 * a1[nt][3], 0.f) + d2v.y);
        }
    }
    __syncthreads();

    // T-stage with folded scores + u-pack. F fp32, X packed (in/out).
    auto t_stage = [&](const float* F, uint32_t* X, int par, int nw) {
        mbar_wait(mb, par);
        float acc[4][4] = {};
        mma_block(X, WH, WL, acc, rb, c32, g, t);
        __syncthreads();
        prefetch(nw);
        float s0a = 0.f, s1a = 0.f, s0b = 0.f, s1b = 0.f;
#pragma unroll
        for (int nt = 0; nt < 4; nt++) {
            int c = cb + nt * 8;
            float2 f1v = *(const float2*)(F + r1 * LDW + c);
            float2 f2v = *(const float2*)(F + r2 * LDW + c);
            float2 x1v = unpack2(*(const uint2*)(X + r1 * LDW + c));
            float2 x2v = unpack2(*(const uint2*)(X + r2 * LDW + c));
            s0a += acc[nt][0] * f1v.x + acc[nt][1] * f1v.y;
            s1a += acc[nt][0] * x1v.x + acc[nt][1] * x1v.y;
            s0b += acc[nt][2] * f2v.x + acc[nt][3] * f2v.y;
            s1b += acc[nt][2] * x2v.x + acc[nt][3] * x2v.y;
        }
#pragma unroll
        for (int o = 1; o < 4; o <<= 1) {  // reduce over t-group
            s0a += __shfl_xor_sync(~0u, s0a, o);
            s1a += __shfl_xor_sync(~0u, s1a, o);
            s0b += __shfl_xor_sync(~0u, s0b, o);
            s1b += __shfl_xor_sync(~0u, s1b, o);
        }
        if (t == 0) {
            red0[c32 * 64 + r1] = s0a;
            red1[c32 * 64 + r1] = s1a;
            red0[c32 * 64 + r2] = s0b;
            red1[c32 * 64 + r2] = s1b;
        }
        __syncthreads();
        if (tid < 64) {
            float S0 = red0[tid] + red0[64 + tid] + red0[128 + tid] + red0[192 + tid];
            float S1 = red1[tid] + red1[64 + tid] + red1[128 + tid] + red1[192 + tid];
            float mx = fmaxf(S0, S1);
            float e0 = expf(S0 - mx), e1 = expf(S1 - mx);
            float inv = 1.f / (e0 + e1);
            w0B[tid] = e0 * inv;
            w1B[tid] = e1 * inv;
        }
        __syncthreads();
#pragma unroll
        for (int rr = 0; rr < 4; rr++) {  // u-pack (warp-4-rows mapping)
            int r = row4 + rr;
            float w0 = w0B[r], w1 = w1B[r];
            float2 f0v = *(const float2*)(F + r * LDW + 2 * lane);
            float2 f1v = *(const float2*)(F + r * LDW + 2 * lane + 64);
            float2 x0v = unpack2(*(const uint2*)(X + r * LDW + 2 * lane));
            float2 x1v = unpack2(*(const uint2*)(X + r * LDW + 2 * lane + 64));
            *(uint2*)(X + r * LDW + 2 * lane) = pack2(w0 * f0v.x + w1 * x0v.x, w0 * f0v.y + w1 * x0v.y);
            *(uint2*)(X + r * LDW + 2 * lane + 64) =
                pack2(w0 * f1v.x + w1 * x1v.x, w0 * f1v.y + w1 * x1v.y);
        }
        __syncthreads();
    };

    // ---------------- m branch ----------------
    t_stage(F0, R2, 1, 2);  // u_m -> R2
    mbar_wait(mb, 0);       // Wvm
    {
        float acc[4][4] = {};
        mma_block(R2, WH, WL, acc, rb, c32, g, t);
        __syncthreads();
        prefetch(3);
#pragma unroll
        for (int nt = 0; nt < 4; nt++) {  // mLA -> F0
            int c = cb + nt * 8;
            *(float2*)(F0 + r1 * LDW + c) = make_float2(acc[nt][0], acc[nt][1]);
            *(float2*)(F0 + r2 * LDW + c) = make_float2(acc[nt][2], acc[nt][3]);
        }
    }
    __syncthreads();

    // ---------------- d branch ----------------
    t_stage(F1, R3, 1, 4);  // u_d -> R3
    mbar_wait(mb, 0);       // Wvd
    {
        float acc[4][4] = {};
        mma_block(R3, WH, WL, acc, rb, c32, g, t);
        __syncthreads();
        prefetch(5);
#pragma unroll
        for (int nt = 0; nt < 4; nt++) {  // ne = mLA * dLA -> R2 packed
            int c = cb + nt * 8;
            float2 m1v = *(const float2*)(F0 + r1 * LDW + c);
            float2 m2v = *(const float2*)(F0 + r2 * LDW + c);
            *(uint2*)(R2 + r1 * LDW + c) = pack2(acc[nt][0] * m1v.x, acc[nt][1] * m1v.y);
            *(uint2*)(R2 + r2 * LDW + c) = pack2(acc[nt][2] * m2v.x, acc[nt][3] * m2v.y);
        }
    }
    __syncthreads();

    // ---------------- head ----------------
    mbar_wait(mb, 1);  // W1
    {
        float acc[4][4] = {};
        mma_block(R2, WH, WL, acc, rb, c32, g, t);
        float pa = 0.f, pb = 0.f;
#pragma unroll
        for (int nt = 0; nt < 4; nt++) {
            int c = cb + nt * 8;
            float2 wv = *(const float2*)(sW2 + c);
            pa += fmaxf(acc[nt][0], 0.f) * wv.x + fmaxf(acc[nt][1], 0.f) * wv.y;
            pb += fmaxf(acc[nt][2], 0.f) * wv.x + fmaxf(acc[nt][3], 0.f) * wv.y;
        }
#pragma unroll
        for (int o = 1; o < 4; o <<= 1) {
            pa += __shfl_xor_sync(~0u, pa, o);
            pb += __shfl_xor_sync(~0u, pb, o);
        }
        __syncthreads();
        if (t == 0) {
            red0[c32 * 64 + r1] = pa;
            red0[c32 * 64 + r2] = pb;
        }
        __syncthreads();
        if (tid < 64) {
            float P = red0[tid] + red0[64 + tid] + red0[128 + tid] + red0[192 + tid];
            out[base + tid] = 1.f / (1.f + expf(-P));
        }
    }
}

// ---------------------------------------------------------------------------
extern "C" void kernel_launch(void* const* d_in, const int* in_sizes, int n_in,
                              void* d_out, int out_size) {
    const float* em    = (const float*)d_in[0];
    const float* ed    = (const float*)d_in[1];
    const float* W_gcn = (const float*)d_in[2];
    const float* Wq_m  = (const float*)d_in[3];
    const float* Wk_m  = (const float*)d_in[4];
    const float* Wv_m  = (const float*)d_in[5];
    const float* Wq_d  = (const float*)d_in[6];
    const float* Wk_d  = (const float*)d_in[7];
    const float* Wv_d  = (const float*)d_in[8];
    const float* W1    = (const float*)d_in[9];
    const float* W2    = (const float*)d_in[10];
    float* out = (float*)d_out;

    const int B = in_sizes[0] / C;
    const int smem_bytes = U_TOT * 4;  // 208448

    precompute_M_kernel<<<dim3(C, 2), C>>>(Wq_m, Wk_m, Wq_d, Wk_d);
    bake_kernel<<<dim3(8192 / 256, 6), 256>>>(W_gcn, Wv_m, Wv_d, W1);

    cudaFuncSetAttribute(fused_kernel,
                         cudaFuncAttributeMaxDynamicSharedMemorySize, smem_bytes);
    fused_kernel<<<B / 64, THREADS, smem_bytes>>>(em, ed, W2, out);
}